// round 16
// baseline (speedup 1.0000x reference)
#include <cuda_runtime.h>
#include <cstdint>

#define N_TOKENS   262144
#define N_EXPERTS  256
#define TOP_K      8

#define LOGITS_ELEMS   ((size_t)N_TOKENS * N_EXPERTS)   // 67108864
#define TOPK_ELEMS     ((size_t)N_TOKENS * TOP_K)       // 2097152

#define BLOCKS   592            // 148 SMs * 4 blocks -> single even wave
#define THREADS  256
#define WARPS_PER_BLOCK (THREADS / 32)
#define MAX_SURV 16

// float -> order-preserving uint key (finite floats)
__device__ __forceinline__ unsigned f2key(float f) {
    unsigned u = __float_as_uint(f);
    return u ^ (0x80000000u | (unsigned)((int)u >> 31));
}
__device__ __forceinline__ float key2f(unsigned k) {
    unsigned u = (k & 0x80000000u) ? (k ^ 0x80000000u) : ~k;
    return __uint_as_float(u);
}

__global__ void zero_hist_kernel(float* __restrict__ hist_out) {
    hist_out[threadIdx.x] = 0.0f;
}

// Single-token tail (fast path + exact fallback), used on the rare (~2%)
// iterations where not both tokens of a pair qualify for the dual fast path.
__device__ __forceinline__ void tail_one(
    int tok, float4 a, float4 b, unsigned g0key, float T0f,
    int total, int base, uint2* buf,
    float* __restrict__ outW, float* __restrict__ outI,
    int* s_hist, int lane)
{
    float f0=a.x, f1=a.y, f2=a.z, f3=a.w, f4=b.x, f5=b.y, f6=b.z, f7=b.w;
    const unsigned ibase = 8u * lane;   // lane L owns contiguous [8L, 8L+8)

    if (total <= MAX_SURV && total >= TOP_K) {
        bool p0=f0>=T0f, p1=f1>=T0f, p2=f2>=T0f, p3=f3>=T0f;
        bool p4=f4>=T0f, p5=f5>=T0f, p6=f6>=T0f, p7=f7>=T0f;
        __syncwarp();
        int c = base;
        if (p0) buf[c++] = make_uint2(__float_as_uint(f0), ibase + 0u);
        if (p1) buf[c++] = make_uint2(__float_as_uint(f1), ibase + 1u);
        if (p2) buf[c++] = make_uint2(__float_as_uint(f2), ibase + 2u);
        if (p3) buf[c++] = make_uint2(__float_as_uint(f3), ibase + 3u);
        if (p4) buf[c++] = make_uint2(__float_as_uint(f4), ibase + 4u);
        if (p5) buf[c++] = make_uint2(__float_as_uint(f5), ibase + 5u);
        if (p6) buf[c++] = make_uint2(__float_as_uint(f6), ibase + 6u);
        if (p7) buf[c++] = make_uint2(__float_as_uint(f7), ibase + 7u);
        __syncwarp();

        // buf order == idx order -> 32-bit keys; ties -> lower group-lane wins
        uint2 sv2  = buf[lane & (MAX_SURV - 1)];
        bool valid = lane < total;
        unsigned kk = valid ? f2key(__uint_as_float(sv2.x)) : 0u;
        const int gl = lane & (MAX_SURV - 1);
        int rank = 0;
        #pragma unroll
        for (int d = 1; d < MAX_SURV; d++) {
            unsigned ok = __shfl_xor_sync(0xffffffffu, kk, d, MAX_SURV);
            rank += (ok > kk) || ((ok == kk) && ((gl ^ d) < gl));
        }
        bool win8 = valid && (rank < TOP_K);
        float vmax = key2f(g0key);
        float ex = win8 ? __expf(__uint_as_float(sv2.x) - vmax) : 0.0f;
        float s = ex;
        #pragma unroll
        for (int d = 1; d < MAX_SURV; d <<= 1)
            s += __shfl_xor_sync(0xffffffffu, s, d, MAX_SURV);
        if (win8) {
            unsigned sidx = sv2.y;
            outW[(size_t)tok * TOP_K + rank] = __fdividef(ex, s);
            outI[(size_t)tok * TOP_K + rank] = (float)sidx;
            atomicAdd(&s_hist[sidx], 1);
        }
        __syncwarp();
    } else {
        // exact 8-round selection (lane order == idx order under this mapping)
        unsigned k[8];
        k[0]=f2key(f0); k[1]=f2key(f1); k[2]=f2key(f2); k[3]=f2key(f3);
        k[4]=f2key(f4); k[5]=f2key(f5); k[6]=f2key(f6); k[7]=f2key(f7);

        unsigned lmax = 0; int lslot = 0;
        #pragma unroll
        for (int j = 0; j < 8; j++) { if (k[j] > lmax) { lmax = k[j]; lslot = j; } }

        unsigned mykey = 0; int myidx = 0;
        #pragma unroll
        for (int r = 0; r < TOP_K; r++) {
            unsigned gg  = __reduce_max_sync(0xffffffffu, lmax);
            unsigned bal = __ballot_sync(0xffffffffu, lmax == gg);
            int win   = __ffs(bal) - 1;                  // lowest lane = lowest idx
            int wslot = __shfl_sync(0xffffffffu, lslot, win);
            if (lane == r) { mykey = gg; myidx = win * 8 + wslot; }
            if (lane == win) {
                k[lslot] = 0u;
                lmax = 0; lslot = 0;
                #pragma unroll
                for (int j = 0; j < 8; j++) { if (k[j] > lmax) { lmax = k[j]; lslot = j; } }
            }
        }

        float vmax = key2f(__shfl_sync(0xffffffffu, mykey, 0));
        float myval = (lane < TOP_K) ? key2f(mykey) : vmax;
        float e = __expf(myval - vmax);
        float s = e;
        s += __shfl_xor_sync(0xffffffffu, s, 1);
        s += __shfl_xor_sync(0xffffffffu, s, 2);
        s += __shfl_xor_sync(0xffffffffu, s, 4);
        if (lane < TOP_K) {
            outW[(size_t)tok * TOP_K + lane] = __fdividef(e, s);
            outI[(size_t)tok * TOP_K + lane] = (float)myidx;
            atomicAdd(&s_hist[myidx], 1);
        }
    }
}

__global__ void __launch_bounds__(THREADS, 4)
moe_router_kernel(const float* __restrict__ logits, float* __restrict__ out) {
    __shared__ int   s_hist[N_EXPERTS];
    __shared__ uint2 s_surv[WARPS_PER_BLOCK][2][MAX_SURV];

    const int tid  = threadIdx.x;
    const int lane = tid & 31;
    const int wip  = tid >> 5;
    const int warp_global = blockIdx.x * WARPS_PER_BLOCK + wip;
    const int n_warps     = BLOCKS * WARPS_PER_BLOCK;   // 4736

    s_hist[tid] = 0;
    __syncthreads();

    float* __restrict__ outW = out + LOGITS_ELEMS;
    float* __restrict__ outI = outW + TOPK_ELEMS;
    uint2* buf0 = s_surv[wip][0];
    uint2* buf1 = s_surv[wip][1];

    for (int pair = warp_global; pair < N_TOKENS / 2; pair += n_warps) {
        const int t0 = 2 * pair, t1 = t0 + 1;

        // ---- interleaved front: loads, copies, lane-max, REDUX chains ----
        const float4* row0 = (const float4*)(logits + (size_t)t0 * N_EXPERTS);
        const float4* row1 = (const float4*)(logits + (size_t)t1 * N_EXPERTS);
        float4 a0 = row0[2 * lane], b0 = row0[2 * lane + 1];
        float4 a1 = row1[2 * lane], b1 = row1[2 * lane + 1];

        float4* o0 = (float4*)(out + (size_t)t0 * N_EXPERTS);
        float4* o1 = (float4*)(out + (size_t)t1 * N_EXPERTS);
        o0[2 * lane] = a0; o0[2 * lane + 1] = b0;
        o1[2 * lane] = a1; o1[2 * lane + 1] = b1;

        float m0 = fmaxf(fmaxf(fmaxf(a0.x,a0.y), fmaxf(a0.z,a0.w)),
                         fmaxf(fmaxf(b0.x,b0.y), fmaxf(b0.z,b0.w)));
        float m1 = fmaxf(fmaxf(fmaxf(a1.x,a1.y), fmaxf(a1.z,a1.w)),
                         fmaxf(fmaxf(b1.x,b1.y), fmaxf(b1.z,b1.w)));

        unsigned u0 = f2key(m0), u1 = f2key(m1);
        unsigned ga0 = 0, ga1 = 0, g0 = 0, g1 = 0;
        #pragma unroll
        for (int r = 0; r < TOP_K; r++) {   // two independent chains, overlapped
            g0 = __reduce_max_sync(0xffffffffu, u0);
            g1 = __reduce_max_sync(0xffffffffu, u1);
            if (r == 0) { ga0 = g0; ga1 = g1; }
            u0 = (u0 == g0) ? 0u : u0;
            u1 = (u1 == g1) ? 0u : u1;
        }
        const float T0 = key2f(g0);         // lower bound on t0's 8th-largest
        const float T1 = key2f(g1);

        bool q0=a0.x>=T0, q1=a0.y>=T0, q2=a0.z>=T0, q3=a0.w>=T0;
        bool q4=b0.x>=T0, q5=b0.y>=T0, q6=b0.z>=T0, q7=b0.w>=T0;
        bool r0=a1.x>=T1, r1=a1.y>=T1, r2=a1.z>=T1, r3=a1.w>=T1;
        bool r4=b1.x>=T1, r5=b1.y>=T1, r6=b1.z>=T1, r7=b1.w>=T1;
        int cnt0 = (int)q0+(int)q1+(int)q2+(int)q3+(int)q4+(int)q5+(int)q6+(int)q7;
        int cnt1 = (int)r0+(int)r1+(int)r2+(int)r3+(int)r4+(int)r5+(int)r6+(int)r7;

        // packed prefix scan: both tokens in one chain (fields can't carry)
        int pk  = cnt0 | (cnt1 << 16);
        int pfx = pk;
        #pragma unroll
        for (int d = 1; d < 32; d <<= 1) {
            int t = __shfl_up_sync(0xffffffffu, pfx, d);
            if (lane >= d) pfx += t;
        }
        int tot = __shfl_sync(0xffffffffu, pfx, 31);
        int exc = pfx - pk;
        int base0 = exc & 0xFFFF,  base1 = exc >> 16;
        int total0 = tot & 0xFFFF, total1 = tot >> 16;

        bool fast0 = (total0 >= TOP_K) && (total0 <= MAX_SURV);
        bool fast1 = (total1 >= TOP_K) && (total1 <= MAX_SURV);

        if (fast0 && fast1) {
            // ---- dual fast path (~98%): interleaved compact + rank ----
            const unsigned ibase = 8u * lane;
            int c0 = base0;
            if (q0) buf0[c0++] = make_uint2(__float_as_uint(a0.x), ibase + 0u);
            if (q1) buf0[c0++] = make_uint2(__float_as_uint(a0.y), ibase + 1u);
            if (q2) buf0[c0++] = make_uint2(__float_as_uint(a0.z), ibase + 2u);
            if (q3) buf0[c0++] = make_uint2(__float_as_uint(a0.w), ibase + 3u);
            if (q4) buf0[c0++] = make_uint2(__float_as_uint(b0.x), ibase + 4u);
            if (q5) buf0[c0++] = make_uint2(__float_as_uint(b0.y), ibase + 5u);
            if (q6) buf0[c0++] = make_uint2(__float_as_uint(b0.z), ibase + 6u);
            if (q7) buf0[c0++] = make_uint2(__float_as_uint(b0.w), ibase + 7u);
            int c1 = base1;
            if (r0) buf1[c1++] = make_uint2(__float_as_uint(a1.x), ibase + 0u);
            if (r1) buf1[c1++] = make_uint2(__float_as_uint(a1.y), ibase + 1u);
            if (r2) buf1[c1++] = make_uint2(__float_as_uint(a1.z), ibase + 2u);
            if (r3) buf1[c1++] = make_uint2(__float_as_uint(a1.w), ibase + 3u);
            if (r4) buf1[c1++] = make_uint2(__float_as_uint(b1.x), ibase + 4u);
            if (r5) buf1[c1++] = make_uint2(__float_as_uint(b1.y), ibase + 5u);
            if (r6) buf1[c1++] = make_uint2(__float_as_uint(b1.z), ibase + 6u);
            if (r7) buf1[c1++] = make_uint2(__float_as_uint(b1.w), ibase + 7u);
            __syncwarp();   // order compaction writes before buf reads

            // buf order == idx order -> 32-bit rank keys; tie -> lower lane
            uint2 sva = buf0[lane & (MAX_SURV - 1)];
            uint2 svb = buf1[lane & (MAX_SURV - 1)];
            bool va = lane < total0, vb = lane < total1;
            unsigned ka = va ? f2key(__uint_as_float(sva.x)) : 0u;
            unsigned kb = vb ? f2key(__uint_as_float(svb.x)) : 0u;
            const int gl = lane & (MAX_SURV - 1);
            int rka = 0, rkb = 0;
            #pragma unroll
            for (int d = 1; d < MAX_SURV; d++) {   // independent shuffles, overlap
                unsigned oa = __shfl_xor_sync(0xffffffffu, ka, d, MAX_SURV);
                unsigned ob = __shfl_xor_sync(0xffffffffu, kb, d, MAX_SURV);
                bool tie = (gl ^ d) < gl;          // partner at lower group-lane
                rka += (oa > ka) || ((oa == ka) && tie);
                rkb += (ob > kb) || ((ob == kb) && tie);
            }
            bool wa = va && (rka < TOP_K);
            bool wb = vb && (rkb < TOP_K);
            float exa = wa ? __expf(__uint_as_float(sva.x) - key2f(ga0)) : 0.0f;
            float exb = wb ? __expf(__uint_as_float(svb.x) - key2f(ga1)) : 0.0f;
            float sa = exa, sb = exb;
            #pragma unroll
            for (int d = 1; d < MAX_SURV; d <<= 1) {
                sa += __shfl_xor_sync(0xffffffffu, sa, d, MAX_SURV);
                sb += __shfl_xor_sync(0xffffffffu, sb, d, MAX_SURV);
            }
            if (wa) {
                outW[(size_t)t0 * TOP_K + rka] = __fdividef(exa, sa);
                outI[(size_t)t0 * TOP_K + rka] = (float)sva.y;
                atomicAdd(&s_hist[sva.y], 1);
            }
            if (wb) {
                outW[(size_t)t1 * TOP_K + rkb] = __fdividef(exb, sb);
                outI[(size_t)t1 * TOP_K + rkb] = (float)svb.y;
                atomicAdd(&s_hist[svb.y], 1);
            }
            // no trailing __syncwarp: the next iteration's full-mask REDUX
            // chain + scan shuffles force convergence before buf is rewritten
        } else {
            // ---- rare: sequential single-token processing (proven paths) ----
            tail_one(t0, a0, b0, ga0, T0, total0, base0, buf0, outW, outI, s_hist, lane);
            tail_one(t1, a1, b1, ga1, T1, total1, base1, buf1, outW, outI, s_hist, lane);
        }
    }

    __syncthreads();
    float* __restrict__ outH = out + LOGITS_ELEMS + 2 * TOPK_ELEMS;
    int c = s_hist[tid];
    if (c > 0) atomicAdd(&outH[tid], (float)c);
}

extern "C" void kernel_launch(void* const* d_in, const int* in_sizes, int n_in,
                              void* d_out, int out_size) {
    const float* logits = (const float*)d_in[0];
    float* out = (float*)d_out;

    float* hist_region = out + LOGITS_ELEMS + 2 * TOPK_ELEMS;
    zero_hist_kernel<<<1, N_EXPERTS>>>(hist_region);
    moe_router_kernel<<<BLOCKS, THREADS>>>(logits, out);
}

// round 17
// speedup vs baseline: 1.0855x; 1.0855x over previous
#include <cuda_runtime.h>
#include <cstdint>

#define N_TOKENS   262144
#define N_EXPERTS  256
#define TOP_K      8

#define LOGITS_ELEMS   ((size_t)N_TOKENS * N_EXPERTS)   // 67108864
#define TOPK_ELEMS     ((size_t)N_TOKENS * TOP_K)       // 2097152

#define BLOCKS   1332           // 148 SMs * 9 blocks -> single even wave
#define THREADS  128
#define WARPS_PER_BLOCK (THREADS / 32)
#define MAX_SURV 16

#define NEG_INF_F  __int_as_float(0xff800000)

// float -> order-preserving uint key (finite floats)
__device__ __forceinline__ unsigned f2key(float f) {
    unsigned u = __float_as_uint(f);
    return u ^ (0x80000000u | (unsigned)((int)u >> 31));
}
__device__ __forceinline__ float key2f(unsigned k) {
    unsigned u = (k & 0x80000000u) ? (k ^ 0x80000000u) : ~k;
    return __uint_as_float(u);
}

__global__ void zero_hist_kernel(float* __restrict__ hist_out) {
    hist_out[threadIdx.x] = 0.0f;
}

// Single-token tail (fast path + exact fallback), rare (~2%).
__device__ __forceinline__ void tail_one(
    int tok, float4 a, float4 b, unsigned g0key, float T0f,
    int total, int base, uint2* buf,
    float* __restrict__ outW, float* __restrict__ outI,
    int* s_hist, int lane)
{
    float f0=a.x, f1=a.y, f2=a.z, f3=a.w, f4=b.x, f5=b.y, f6=b.z, f7=b.w;
    const unsigned ibase = 8u * lane;   // lane L owns contiguous [8L, 8L+8)

    if (total <= MAX_SURV && total >= TOP_K) {
        __syncwarp();
        int c = base;
        if (f0 >= T0f) buf[c++] = make_uint2(__float_as_uint(f0), ibase + 0u);
        if (f1 >= T0f) buf[c++] = make_uint2(__float_as_uint(f1), ibase + 1u);
        if (f2 >= T0f) buf[c++] = make_uint2(__float_as_uint(f2), ibase + 2u);
        if (f3 >= T0f) buf[c++] = make_uint2(__float_as_uint(f3), ibase + 3u);
        if (f4 >= T0f) buf[c++] = make_uint2(__float_as_uint(f4), ibase + 4u);
        if (f5 >= T0f) buf[c++] = make_uint2(__float_as_uint(f5), ibase + 5u);
        if (f6 >= T0f) buf[c++] = make_uint2(__float_as_uint(f6), ibase + 6u);
        if (f7 >= T0f) buf[c++] = make_uint2(__float_as_uint(f7), ibase + 7u);
        __syncwarp();

        // buf order == idx order -> float rank; ties -> lower group-lane wins
        uint2 sv2  = buf[lane & (MAX_SURV - 1)];
        bool valid = lane < total;
        float mv = valid ? __uint_as_float(sv2.x) : NEG_INF_F;
        const int gl = lane & (MAX_SURV - 1);
        int rank = 0;
        #pragma unroll
        for (int d = 1; d < MAX_SURV; d++) {
            float ov = __shfl_xor_sync(0xffffffffu, mv, d, MAX_SURV);
            bool tie = (gl ^ d) < gl;              // compile-time per d
            rank += (ov > mv) || ((ov == mv) && tie);
        }
        bool win8 = valid && (rank < TOP_K);
        float ex = win8 ? __expf(mv - key2f(g0key)) : 0.0f;
        float s = ex;
        #pragma unroll
        for (int d = 1; d < MAX_SURV; d <<= 1)
            s += __shfl_xor_sync(0xffffffffu, s, d, MAX_SURV);
        if (win8) {
            unsigned sidx = sv2.y;
            outW[(size_t)tok * TOP_K + rank] = __fdividef(ex, s);
            outI[(size_t)tok * TOP_K + rank] = (float)sidx;
            atomicAdd(&s_hist[sidx], 1);
        }
        __syncwarp();
    } else {
        // exact 8-round selection (lane order == idx order under this mapping)
        unsigned k[8];
        k[0]=f2key(f0); k[1]=f2key(f1); k[2]=f2key(f2); k[3]=f2key(f3);
        k[4]=f2key(f4); k[5]=f2key(f5); k[6]=f2key(f6); k[7]=f2key(f7);

        unsigned lmax = 0; int lslot = 0;
        #pragma unroll
        for (int j = 0; j < 8; j++) { if (k[j] > lmax) { lmax = k[j]; lslot = j; } }

        unsigned mykey = 0; int myidx = 0;
        #pragma unroll
        for (int r = 0; r < TOP_K; r++) {
            unsigned gg  = __reduce_max_sync(0xffffffffu, lmax);
            unsigned bal = __ballot_sync(0xffffffffu, lmax == gg);
            int win   = __ffs(bal) - 1;                  // lowest lane = lowest idx
            int wslot = __shfl_sync(0xffffffffu, lslot, win);
            if (lane == r) { mykey = gg; myidx = win * 8 + wslot; }
            if (lane == win) {
                k[lslot] = 0u;
                lmax = 0; lslot = 0;
                #pragma unroll
                for (int j = 0; j < 8; j++) { if (k[j] > lmax) { lmax = k[j]; lslot = j; } }
            }
        }

        float vmax = key2f(__shfl_sync(0xffffffffu, mykey, 0));
        float myval = (lane < TOP_K) ? key2f(mykey) : vmax;
        float e = __expf(myval - vmax);
        float s = e;
        s += __shfl_xor_sync(0xffffffffu, s, 1);
        s += __shfl_xor_sync(0xffffffffu, s, 2);
        s += __shfl_xor_sync(0xffffffffu, s, 4);
        if (lane < TOP_K) {
            outW[(size_t)tok * TOP_K + lane] = __fdividef(e, s);
            outI[(size_t)tok * TOP_K + lane] = (float)myidx;
            atomicAdd(&s_hist[myidx], 1);
        }
    }
}

__global__ void __launch_bounds__(THREADS, 9)
moe_router_kernel(const float* __restrict__ logits, float* __restrict__ out) {
    __shared__ int   s_hist[N_EXPERTS];
    __shared__ uint2 s_surv[WARPS_PER_BLOCK][2][MAX_SURV];

    const int tid  = threadIdx.x;
    const int lane = tid & 31;
    const int wip  = tid >> 5;
    const int warp_global = blockIdx.x * WARPS_PER_BLOCK + wip;
    const int n_warps     = BLOCKS * WARPS_PER_BLOCK;   // 5328

    #pragma unroll
    for (int i = tid; i < N_EXPERTS; i += THREADS) s_hist[i] = 0;
    __syncthreads();

    float* __restrict__ outW = out + LOGITS_ELEMS;
    float* __restrict__ outI = outW + TOPK_ELEMS;
    uint2* buf0 = s_surv[wip][0];
    uint2* buf1 = s_surv[wip][1];

    for (int pair = warp_global; pair < N_TOKENS / 2; pair += n_warps) {
        const int t0 = 2 * pair, t1 = t0 + 1;

        // ---- interleaved front: loads, copies, lane-max, REDUX chains ----
        const float4* row0 = (const float4*)(logits + (size_t)t0 * N_EXPERTS);
        const float4* row1 = (const float4*)(logits + (size_t)t1 * N_EXPERTS);
        float4 a0 = row0[2 * lane], b0 = row0[2 * lane + 1];
        float4 a1 = row1[2 * lane], b1 = row1[2 * lane + 1];

        float4* o0 = (float4*)(out + (size_t)t0 * N_EXPERTS);
        float4* o1 = (float4*)(out + (size_t)t1 * N_EXPERTS);
        o0[2 * lane] = a0; o0[2 * lane + 1] = b0;
        o1[2 * lane] = a1; o1[2 * lane + 1] = b1;

        float m0 = fmaxf(fmaxf(fmaxf(a0.x,a0.y), fmaxf(a0.z,a0.w)),
                         fmaxf(fmaxf(b0.x,b0.y), fmaxf(b0.z,b0.w)));
        float m1 = fmaxf(fmaxf(fmaxf(a1.x,a1.y), fmaxf(a1.z,a1.w)),
                         fmaxf(fmaxf(b1.x,b1.y), fmaxf(b1.z,b1.w)));

        unsigned u0 = f2key(m0), u1 = f2key(m1);
        unsigned ga0 = 0, ga1 = 0, g0 = 0, g1 = 0;
        #pragma unroll
        for (int r = 0; r < TOP_K; r++) {   // two independent chains, overlapped
            g0 = __reduce_max_sync(0xffffffffu, u0);
            g1 = __reduce_max_sync(0xffffffffu, u1);
            if (r == 0) { ga0 = g0; ga1 = g1; }
            u0 = (u0 == g0) ? 0u : u0;
            u1 = (u1 == g1) ? 0u : u1;
        }
        const float T0 = key2f(g0);         // lower bound on t0's 8th-largest
        const float T1 = key2f(g1);

        // survivor counts (predicates recomputed later at compaction to keep
        // register pressure low for the 9-block occupancy target)
        int cnt0 = (int)(a0.x>=T0)+(int)(a0.y>=T0)+(int)(a0.z>=T0)+(int)(a0.w>=T0)
                 + (int)(b0.x>=T0)+(int)(b0.y>=T0)+(int)(b0.z>=T0)+(int)(b0.w>=T0);
        int cnt1 = (int)(a1.x>=T1)+(int)(a1.y>=T1)+(int)(a1.z>=T1)+(int)(a1.w>=T1)
                 + (int)(b1.x>=T1)+(int)(b1.y>=T1)+(int)(b1.z>=T1)+(int)(b1.w>=T1);

        // packed prefix scan: both tokens in one chain (fields can't carry)
        int pk  = cnt0 | (cnt1 << 16);
        int pfx = pk;
        #pragma unroll
        for (int d = 1; d < 32; d <<= 1) {
            int t = __shfl_up_sync(0xffffffffu, pfx, d);
            if (lane >= d) pfx += t;
        }
        int tot = __shfl_sync(0xffffffffu, pfx, 31);
        int exc = pfx - pk;
        int base0 = exc & 0xFFFF,  base1 = exc >> 16;
        int total0 = tot & 0xFFFF, total1 = tot >> 16;

        bool fast0 = (total0 >= TOP_K) && (total0 <= MAX_SURV);
        bool fast1 = (total1 >= TOP_K) && (total1 <= MAX_SURV);

        if (fast0 && fast1) {
            // ---- dual fast path (~98%): interleaved compact + rank ----
            const unsigned ibase = 8u * lane;
            int c0 = base0;
            if (a0.x >= T0) buf0[c0++] = make_uint2(__float_as_uint(a0.x), ibase + 0u);
            if (a0.y >= T0) buf0[c0++] = make_uint2(__float_as_uint(a0.y), ibase + 1u);
            if (a0.z >= T0) buf0[c0++] = make_uint2(__float_as_uint(a0.z), ibase + 2u);
            if (a0.w >= T0) buf0[c0++] = make_uint2(__float_as_uint(a0.w), ibase + 3u);
            if (b0.x >= T0) buf0[c0++] = make_uint2(__float_as_uint(b0.x), ibase + 4u);
            if (b0.y >= T0) buf0[c0++] = make_uint2(__float_as_uint(b0.y), ibase + 5u);
            if (b0.z >= T0) buf0[c0++] = make_uint2(__float_as_uint(b0.z), ibase + 6u);
            if (b0.w >= T0) buf0[c0++] = make_uint2(__float_as_uint(b0.w), ibase + 7u);
            int c1 = base1;
            if (a1.x >= T1) buf1[c1++] = make_uint2(__float_as_uint(a1.x), ibase + 0u);
            if (a1.y >= T1) buf1[c1++] = make_uint2(__float_as_uint(a1.y), ibase + 1u);
            if (a1.z >= T1) buf1[c1++] = make_uint2(__float_as_uint(a1.z), ibase + 2u);
            if (a1.w >= T1) buf1[c1++] = make_uint2(__float_as_uint(a1.w), ibase + 3u);
            if (b1.x >= T1) buf1[c1++] = make_uint2(__float_as_uint(b1.x), ibase + 4u);
            if (b1.y >= T1) buf1[c1++] = make_uint2(__float_as_uint(b1.y), ibase + 5u);
            if (b1.z >= T1) buf1[c1++] = make_uint2(__float_as_uint(b1.z), ibase + 6u);
            if (b1.w >= T1) buf1[c1++] = make_uint2(__float_as_uint(b1.w), ibase + 7u);
            __syncwarp();   // order compaction writes before buf reads

            // buf order == idx order -> FLOAT rank (FSETP on fma pipe);
            // ties -> lower group-lane (= lower idx) wins
            uint2 sva = s_surv[wip][0][lane & (MAX_SURV - 1)];
            uint2 svb = s_surv[wip][1][lane & (MAX_SURV - 1)];
            bool va = lane < total0, vb = lane < total1;
            float mva = va ? __uint_as_float(sva.x) : NEG_INF_F;
            float mvb = vb ? __uint_as_float(svb.x) : NEG_INF_F;
            const int gl = lane & (MAX_SURV - 1);
            int rka = 0, rkb = 0;
            #pragma unroll
            for (int d = 1; d < MAX_SURV; d++) {   // independent shuffles, overlap
                float oa = __shfl_xor_sync(0xffffffffu, mva, d, MAX_SURV);
                float ob = __shfl_xor_sync(0xffffffffu, mvb, d, MAX_SURV);
                bool tie = (gl ^ d) < gl;          // compile-time per d
                rka += (oa > mva) || ((oa == mva) && tie);
                rkb += (ob > mvb) || ((ob == mvb) && tie);
            }
            bool wa = va && (rka < TOP_K);
            bool wb = vb && (rkb < TOP_K);
            float exa = wa ? __expf(mva - key2f(ga0)) : 0.0f;
            float exb = wb ? __expf(mvb - key2f(ga1)) : 0.0f;
            float sa = exa, sb = exb;
            #pragma unroll
            for (int d = 1; d < MAX_SURV; d <<= 1) {
                sa += __shfl_xor_sync(0xffffffffu, sa, d, MAX_SURV);
                sb += __shfl_xor_sync(0xffffffffu, sb, d, MAX_SURV);
            }
            if (wa) {
                outW[(size_t)t0 * TOP_K + rka] = __fdividef(exa, sa);
                outI[(size_t)t0 * TOP_K + rka] = (float)sva.y;
                atomicAdd(&s_hist[sva.y], 1);
            }
            if (wb) {
                outW[(size_t)t1 * TOP_K + rkb] = __fdividef(exb, sb);
                outI[(size_t)t1 * TOP_K + rkb] = (float)svb.y;
                atomicAdd(&s_hist[svb.y], 1);
            }
            __syncwarp();   // protect buf across loop iterations
        } else {
            // ---- rare: sequential single-token processing (proven paths) ----
            tail_one(t0, a0, b0, ga0, T0, total0, base0, buf0, outW, outI, s_hist, lane);
            tail_one(t1, a1, b1, ga1, T1, total1, base1, buf1, outW, outI, s_hist, lane);
        }
    }

    __syncthreads();
    float* __restrict__ outH = out + LOGITS_ELEMS + 2 * TOPK_ELEMS;
    #pragma unroll
    for (int i = tid; i < N_EXPERTS; i += THREADS) {
        int c = s_hist[i];
        if (c > 0) atomicAdd(&outH[i], (float)c);
    }
}

extern "C" void kernel_launch(void* const* d_in, const int* in_sizes, int n_in,
                              void* d_out, int out_size) {
    const float* logits = (const float*)d_in[0];
    float* out = (float*)d_out;

    float* hist_region = out + LOGITS_ELEMS + 2 * TOPK_ELEMS;
    zero_hist_kernel<<<1, N_EXPERTS>>>(hist_region);
    moe_router_kernel<<<BLOCKS, THREADS>>>(logits, out);
}